// round 4
// baseline (speedup 1.0000x reference)
#include <cuda_runtime.h>
#include <cuda_bf16.h>

typedef unsigned short u16;
typedef unsigned int   u32;

#define BB 32
#define NN 512
#define DD 512
#define NH 8
#define DH 64
#define BH (BB*NH)       // 256
#define MROWS (BB*NN)    // 16384
#define PKROW 1024       // packed row: 512 cols -> 16 blocks of [hi32|lo32] u16

// epilogue flags
#define F_F32   1
#define F_PK    2
#define F_BCOL  4
#define F_BROW  8
#define F_RELU  16
#define F_RESID 32

// ---------------- scratch (__device__ globals; no allocations) ----------------
__device__ u16  g_inq [MROWS*PKROW];
__device__ u16  g_ink [MROWS*PKROW];
__device__ u16  g_wq  [DD*PKROW];
__device__ u16  g_wk  [DD*PKROW];
__device__ u16  g_wv  [DD*PKROW];
__device__ u16  g_wo  [DD*PKROW];
__device__ u16  g_w1  [DD*PKROW];
__device__ u16  g_w2  [DD*PKROW];
__device__ u16  g_qp  [MROWS*PKROW];
__device__ u16  g_kp  [MROWS*PKROW];
__device__ u16  g_vT  [MROWS*PKROW];      // [b][d=512][tokens packed]
__device__ u16  g_Pp  [134217728];        // [z=256][q=512][PKROW]
__device__ u16  g_at  [MROWS*PKROW];
__device__ u16  g_op  [MROWS*PKROW];
__device__ u16  g_h1  [MROWS*PKROW];
__device__ float  g_sc  [67108864];       // [z][q][k] fp32 scores
__device__ float  g_of  [MROWS*DD];       // out fp32 (residual source)
__device__ float2 g_st  [BH*NN];          // per (z,k): (max, 1/sum)

// ---------------- helpers ----------------
__device__ __forceinline__ void split2(float x, float y, u32 &h, u32 &l) {
    __nv_bfloat16 hx = __float2bfloat16(x);
    __nv_bfloat16 hy = __float2bfloat16(y);
    __nv_bfloat16 lx = __float2bfloat16(x - __bfloat162float(hx));
    __nv_bfloat16 ly = __float2bfloat16(y - __bfloat162float(hy));
    __nv_bfloat162 H; H.x = hx; H.y = hy;
    __nv_bfloat162 L; L.x = lx; L.y = ly;
    h = *(u32*)&H; l = *(u32*)&L;
}

__device__ __forceinline__ void mma_bf16(float* c, const u32* a, const u32* b) {
    asm volatile(
        "mma.sync.aligned.m16n8k16.row.col.f32.bf16.bf16.f32 "
        "{%0,%1,%2,%3}, {%4,%5,%6,%7}, {%8,%9}, {%0,%1,%2,%3};\n"
        : "+f"(c[0]), "+f"(c[1]), "+f"(c[2]), "+f"(c[3])
        : "r"(a[0]), "r"(a[1]), "r"(a[2]), "r"(a[3]), "r"(b[0]), "r"(b[1]));
}

__device__ __forceinline__ void ldsm4(u32 &r0, u32 &r1, u32 &r2, u32 &r3, const u16* p) {
    u32 a = (u32)__cvta_generic_to_shared(p);
    asm volatile("ldmatrix.sync.aligned.m8n8.x4.shared.b16 {%0,%1,%2,%3}, [%4];\n"
                 : "=r"(r0), "=r"(r1), "=r"(r2), "=r"(r3) : "r"(a));
}

__device__ __forceinline__ void cp16(u16* dst, const u16* src) {
    u32 d = (u32)__cvta_generic_to_shared(dst);
    asm volatile("cp.async.cg.shared.global [%0], [%1], 16;\n" :: "r"(d), "l"(src));
}

// ---------------- prep: fp32 -> packed hi/lo bf16 (rows of 512) ----------------
__global__ void __launch_bounds__(256) split_pack(const float* __restrict__ src,
                                                  u16* __restrict__ dst, int total4) {
    int i = blockIdx.x * 256 + threadIdx.x;
    if (i >= total4) return;
    int m = i >> 7;            // 128 float4 per row
    int k = (i & 127) << 2;
    float4 f = ((const float4*)src)[i];
    long off = (long)m * PKROW + ((k >> 5) << 6) + (k & 31);
    u32 h0, l0, h1, l1;
    split2(f.x, f.y, h0, l0);
    split2(f.z, f.w, h1, l1);
    *(u32*)(dst + off)      = h0;
    *(u32*)(dst + off + 2)  = h1;
    *(u32*)(dst + off + 32) = l0;
    *(u32*)(dst + off + 34) = l1;
}

// ---------------- generic packed NT GEMM, cp.async 3-stage + ldmatrix ----------
template<int BN, int FL>
__global__ void __launch_bounds__(256, 1) gemm_pk(
    const u16* __restrict__ Ap, long aRow, long aZb, long aZh,
    const u16* __restrict__ Bp, long bRow, long bZb, long bZh,
    float* __restrict__ Cf, int ldcf, long cfZb, long cfZh,
    u16* __restrict__ Cp, long cpRow, long cpZb, long cpZh,
    const float* __restrict__ bias,
    const float* __restrict__ Rres,
    float alpha, int K, int Hh)
{
    constexpr int ST  = 3;
    constexpr int MF  = (BN == 128) ? 4 : 2;
    constexpr int ASZ = 128 * 64;       // u16 per A stage
    constexpr int BSZ = BN * 64;

    extern __shared__ u16 sm[];
    u16* sA = sm;
    u16* sB = sm + ST * ASZ;

    const int z  = blockIdx.z;
    const int zb = z / Hh;
    const int zh = z - zb * Hh;
    const u16* Ag = Ap + (long)zb * aZb + (long)zh * aZh + (long)blockIdx.y * 128 * aRow;
    const u16* Bg = Bp + (long)zb * bZb + (long)zh * bZh + (long)blockIdx.x * BN * bRow;

    const int tid = threadIdx.x;
    const int wid = tid >> 5, lane = tid & 31;
    const int wm  = (BN == 128) ? (wid & 1)  : (wid & 3);
    const int wn  = (BN == 128) ? (wid >> 1) : (wid >> 2);
    const int WMb = wm * ((BN == 128) ? 64 : 32);
    const int WNb = wn * 32;
    const int mi  = lane >> 3;
    // ldmatrix lane addressing (constant per thread)
    const int arb = WMb + ((mi & 1) << 3) + (lane & 7);
    const int ar7 = arb & 7;
    const int cA  = mi >> 1;
    const int brb = WNb + ((mi >> 1) << 3) + (lane & 7);
    const int br7 = brb & 7;
    const int cB  = mi & 1;

    float acc[MF][4][4];
    #pragma unroll
    for (int a = 0; a < MF; a++)
        #pragma unroll
        for (int b = 0; b < 4; b++)
            #pragma unroll
            for (int c = 0; c < 4; c++) acc[a][b][c] = 0.f;

    const int KT = K >> 5;

    // prologue: stages 0..ST-2
    #pragma unroll
    for (int s = 0; s < ST - 1; s++) {
        u16* dA = sA + s * ASZ;
        u16* dB = sB + s * BSZ;
        const u16* gA = Ag + s * 64;
        const u16* gB = Bg + s * 64;
        #pragma unroll
        for (int i = 0; i < 4; i++) {
            int id = i * 256 + tid; int r = id >> 3, c = id & 7;
            cp16(dA + r * 64 + ((c ^ (r & 7)) << 3), gA + (long)r * aRow + c * 8);
        }
        #pragma unroll
        for (int i = 0; i < BN / 32; i++) {
            int id = i * 256 + tid; int r = id >> 3, c = id & 7;
            cp16(dB + r * 64 + ((c ^ (r & 7)) << 3), gB + (long)r * bRow + c * 8);
        }
        asm volatile("cp.async.commit_group;\n");
    }

    #pragma unroll 1
    for (int kt = 0; kt < KT; kt++) {
        asm volatile("cp.async.wait_group %0;\n" :: "n"(ST - 2));
        __syncthreads();
        const u16* As = sA + (kt % ST) * ASZ;
        const u16* Bs = sB + (kt % ST) * BSZ;

        #pragma unroll
        for (int s = 0; s < 2; s++) {
            u32 ah[MF][4], al[MF][4], bh[4][2], bl[4][2];
            #pragma unroll
            for (int mf = 0; mf < MF; mf++) {
                const u16* base = As + (arb + mf * 16) * 64;
                ldsm4(ah[mf][0], ah[mf][1], ah[mf][2], ah[mf][3],
                      base + (((2 * s + cA) ^ ar7) << 3));
                ldsm4(al[mf][0], al[mf][1], al[mf][2], al[mf][3],
                      base + (((4 + 2 * s + cA) ^ ar7) << 3));
            }
            #pragma unroll
            for (int g = 0; g < 2; g++) {
                const u16* base = Bs + (brb + g * 16) * 64;
                u32 r0, r1, r2, r3;
                ldsm4(r0, r1, r2, r3, base + (((2 * s + cB) ^ br7) << 3));
                bh[g*2][0] = r0; bh[g*2][1] = r1; bh[g*2+1][0] = r2; bh[g*2+1][1] = r3;
                ldsm4(r0, r1, r2, r3, base + (((4 + 2 * s + cB) ^ br7) << 3));
                bl[g*2][0] = r0; bl[g*2][1] = r1; bl[g*2+1][0] = r2; bl[g*2+1][1] = r3;
            }
            #pragma unroll
            for (int mf = 0; mf < MF; mf++)
                #pragma unroll
                for (int nf = 0; nf < 4; nf++) {
                    mma_bf16(acc[mf][nf], ah[mf], bh[nf]);
                    mma_bf16(acc[mf][nf], ah[mf], bl[nf]);
                    mma_bf16(acc[mf][nf], al[mf], bh[nf]);
                }
        }

        int nk = kt + ST - 1;
        if (nk < KT) {
            u16* dA = sA + (nk % ST) * ASZ;
            u16* dB = sB + (nk % ST) * BSZ;
            const u16* gA = Ag + nk * 64;
            const u16* gB = Bg + nk * 64;
            #pragma unroll
            for (int i = 0; i < 4; i++) {
                int id = i * 256 + tid; int r = id >> 3, c = id & 7;
                cp16(dA + r * 64 + ((c ^ (r & 7)) << 3), gA + (long)r * aRow + c * 8);
            }
            #pragma unroll
            for (int i = 0; i < BN / 32; i++) {
                int id = i * 256 + tid; int r = id >> 3, c = id & 7;
                cp16(dB + r * 64 + ((c ^ (r & 7)) << 3), gB + (long)r * bRow + c * 8);
            }
        }
        asm volatile("cp.async.commit_group;\n");
    }

    // ---------------- epilogue ----------------
    const int lg = lane >> 2, lc = lane & 3;
    const int m0  = blockIdx.y * 128;
    const int n0g = blockIdx.x * BN;
    float* Cfz = (FL & F_F32) ? (Cf + (long)zb * cfZb + (long)zh * cfZh) : nullptr;
    u16*   Cpz = (FL & F_PK)  ? (Cp + (long)zb * cpZb + (long)zh * cpZh) : nullptr;

    #pragma unroll
    for (int mf = 0; mf < MF; mf++) {
        int r1 = m0 + WMb + mf * 16 + lg;
        int r2 = r1 + 8;
        float br1 = 0.f, br2 = 0.f;
        if (FL & F_BROW) { br1 = bias[r1]; br2 = bias[r2]; }
        #pragma unroll
        for (int nf = 0; nf < 4; nf++) {
            int n = n0g + WNb + nf * 8 + lc * 2;
            float c0 = acc[mf][nf][0] * alpha, c1 = acc[mf][nf][1] * alpha;
            float c2 = acc[mf][nf][2] * alpha, c3 = acc[mf][nf][3] * alpha;
            if (FL & F_BCOL) {
                float2 bb = *(const float2*)(bias + n);
                c0 += bb.x; c1 += bb.y; c2 += bb.x; c3 += bb.y;
            }
            if (FL & F_BROW) { c0 += br1; c1 += br1; c2 += br2; c3 += br2; }
            if (FL & F_RESID) {
                float2 q1 = *(const float2*)(Rres + (long)r1 * ldcf + n);
                float2 q2 = *(const float2*)(Rres + (long)r2 * ldcf + n);
                c0 += q1.x; c1 += q1.y; c2 += q2.x; c3 += q2.y;
            }
            if (FL & F_RELU) {
                c0 = fmaxf(c0, 0.f); c1 = fmaxf(c1, 0.f);
                c2 = fmaxf(c2, 0.f); c3 = fmaxf(c3, 0.f);
            }
            if (FL & F_F32) {
                *(float2*)(Cfz + (long)r1 * ldcf + n) = make_float2(c0, c1);
                *(float2*)(Cfz + (long)r2 * ldcf + n) = make_float2(c2, c3);
            }
            if (FL & F_PK) {
                u32 h, l;
                long o1 = (long)r1 * cpRow + ((n >> 5) << 6) + (n & 31);
                split2(c0, c1, h, l);
                *(u32*)(Cpz + o1) = h; *(u32*)(Cpz + o1 + 32) = l;
                long o2 = (long)r2 * cpRow + ((n >> 5) << 6) + (n & 31);
                split2(c2, c3, h, l);
                *(u32*)(Cpz + o2) = h; *(u32*)(Cpz + o2 + 32) = l;
            }
        }
    }
}

// ---------------- softmax over QUERY axis ----------------
__global__ void __launch_bounds__(256) softmax_pass1(const float* __restrict__ S,
                                                     float2* __restrict__ stat) {
    const int z = blockIdx.y;
    const int k = blockIdx.x * 256 + threadIdx.x;
    const float* p = S + (long)z * NN * NN + k;
    float mx = -1e30f, s = 0.f;
    #pragma unroll 4
    for (int q = 0; q < NN; q++) {
        float x = p[(long)q * NN];
        float nm = fmaxf(mx, x);
        s = s * __expf(mx - nm) + __expf(x - nm);
        mx = nm;
    }
    stat[z * NN + k] = make_float2(mx, 1.0f / s);
}

__global__ void __launch_bounds__(256) softmax_pass2(const float* __restrict__ S,
                                                     const float2* __restrict__ stat,
                                                     u16* __restrict__ P) {
    const int z = blockIdx.y;
    const int q = blockIdx.x;
    const int k = threadIdx.x * 2;
    float2 x  = *(const float2*)(S + ((long)z * NN + q) * NN + k);
    float2 s0 = stat[z * NN + k];
    float2 s1 = stat[z * NN + k + 1];
    float p0 = __expf(x.x - s0.x) * s0.y;
    float p1 = __expf(x.y - s1.x) * s1.y;
    u32 h, l;
    split2(p0, p1, h, l);
    long off = ((long)z * NN + q) * PKROW + ((k >> 5) << 6) + (k & 31);
    *(u32*)(P + off)      = h;
    *(u32*)(P + off + 32) = l;
}

// ---------------- launch ----------------
extern "C" void kernel_launch(void* const* d_in, const int* in_sizes, int n_in,
                              void* d_out, int out_size)
{
    const float* Q  = (const float*)d_in[0];
    const float* Kx = (const float*)d_in[1];
    const float* Wq = (const float*)d_in[2];
    const float* bq = (const float*)d_in[3];
    const float* Wk = (const float*)d_in[4];
    const float* bk = (const float*)d_in[5];
    const float* Wv = (const float*)d_in[6];
    const float* bv = (const float*)d_in[7];
    const float* Wo = (const float*)d_in[8];
    const float* bo = (const float*)d_in[9];
    const float* W1 = (const float*)d_in[10];
    const float* b1 = (const float*)d_in[11];
    const float* W2 = (const float*)d_in[12];
    const float* b2 = (const float*)d_in[13];
    float* out = (float*)d_out;

    static u16 *p_inq = nullptr, *p_ink, *p_wq, *p_wk, *p_wv, *p_wo, *p_w1, *p_w2;
    static u16 *p_qp, *p_kp, *p_vT, *p_Pp, *p_at, *p_op, *p_h1;
    static float *p_sc, *p_of;
    static float2 *p_st;
    if (!p_inq) {
        cudaGetSymbolAddress((void**)&p_ink, g_ink);
        cudaGetSymbolAddress((void**)&p_wq,  g_wq);
        cudaGetSymbolAddress((void**)&p_wk,  g_wk);
        cudaGetSymbolAddress((void**)&p_wv,  g_wv);
        cudaGetSymbolAddress((void**)&p_wo,  g_wo);
        cudaGetSymbolAddress((void**)&p_w1,  g_w1);
        cudaGetSymbolAddress((void**)&p_w2,  g_w2);
        cudaGetSymbolAddress((void**)&p_qp,  g_qp);
        cudaGetSymbolAddress((void**)&p_kp,  g_kp);
        cudaGetSymbolAddress((void**)&p_vT,  g_vT);
        cudaGetSymbolAddress((void**)&p_Pp,  g_Pp);
        cudaGetSymbolAddress((void**)&p_at,  g_at);
        cudaGetSymbolAddress((void**)&p_op,  g_op);
        cudaGetSymbolAddress((void**)&p_h1,  g_h1);
        cudaGetSymbolAddress((void**)&p_sc,  g_sc);
        cudaGetSymbolAddress((void**)&p_of,  g_of);
        cudaGetSymbolAddress((void**)&p_st,  g_st);

        cudaFuncSetAttribute((const void*)gemm_pk<128, F_PK|F_BCOL>,
                             cudaFuncAttributeMaxDynamicSharedMemorySize, 98304);
        cudaFuncSetAttribute((const void*)gemm_pk<128, F_PK|F_BROW>,
                             cudaFuncAttributeMaxDynamicSharedMemorySize, 98304);
        cudaFuncSetAttribute((const void*)gemm_pk<128, F_F32>,
                             cudaFuncAttributeMaxDynamicSharedMemorySize, 98304);
        cudaFuncSetAttribute((const void*)gemm_pk<64, F_PK>,
                             cudaFuncAttributeMaxDynamicSharedMemorySize, 73728);
        cudaFuncSetAttribute((const void*)gemm_pk<128, F_F32|F_PK|F_BCOL|F_RESID>,
                             cudaFuncAttributeMaxDynamicSharedMemorySize, 98304);
        cudaFuncSetAttribute((const void*)gemm_pk<128, F_PK|F_BCOL|F_RELU>,
                             cudaFuncAttributeMaxDynamicSharedMemorySize, 98304);
        cudaFuncSetAttribute((const void*)gemm_pk<128, F_F32|F_BCOL|F_RESID>,
                             cudaFuncAttributeMaxDynamicSharedMemorySize, 98304);

        cudaGetSymbolAddress((void**)&p_inq, g_inq); // last: guards the others
    }

    const float SCALE = 0.044194173824159216f;  // 1/sqrt(512)

    // prep: split to packed bf16 hi/lo
    split_pack<<<8192, 256>>>(Q,  p_inq, MROWS * 128);
    split_pack<<<8192, 256>>>(Kx, p_ink, MROWS * 128);
    split_pack<<<256, 256>>>(Wq, p_wq, DD * 128);
    split_pack<<<256, 256>>>(Wk, p_wk, DD * 128);
    split_pack<<<256, 256>>>(Wv, p_wv, DD * 128);
    split_pack<<<256, 256>>>(Wo, p_wo, DD * 128);
    split_pack<<<256, 256>>>(W1, p_w1, DD * 128);
    split_pack<<<256, 256>>>(W2, p_w2, DD * 128);

    // q, k projections
    gemm_pk<128, F_PK|F_BCOL><<<dim3(4,128,1), 256, 98304>>>(
        p_inq, PKROW, 0, 0,  p_wq, PKROW, 0, 0,
        nullptr, 0, 0, 0,  p_qp, PKROW, 0, 0,  bq, nullptr, 1.f, 512, 1);
    gemm_pk<128, F_PK|F_BCOL><<<dim3(4,128,1), 256, 98304>>>(
        p_ink, PKROW, 0, 0,  p_wk, PKROW, 0, 0,
        nullptr, 0, 0, 0,  p_kp, PKROW, 0, 0,  bk, nullptr, 1.f, 512, 1);

    // vT[b] = Wv @ Kx[b]^T  (row bias bv)
    gemm_pk<128, F_PK|F_BROW><<<dim3(4,4,32), 256, 98304>>>(
        p_wv, PKROW, 0, 0,  p_ink, PKROW, (long)NN*PKROW, 0,
        nullptr, 0, 0, 0,  p_vT, PKROW, (long)NN*PKROW, 0,  bv, nullptr, 1.f, 512, 1);

    // scores (fp32, scaled)
    gemm_pk<128, F_F32><<<dim3(4,4,256), 256, 98304>>>(
        p_qp, PKROW, (long)NN*PKROW, 2*DH,  p_kp, PKROW, (long)NN*PKROW, 2*DH,
        p_sc, NN, (long)NH*NN*NN, (long)NN*NN,  nullptr, 0, 0, 0,
        nullptr, nullptr, SCALE, DH, NH);

    // softmax over q (per column k), write packed P
    softmax_pass1<<<dim3(2, BH), 256>>>(p_sc, p_st);
    softmax_pass2<<<dim3(NN, BH), 256>>>(p_sc, p_st, p_Pp);

    // attn = P @ vT^T  (per (b,h), BN=64)
    gemm_pk<64, F_PK><<<dim3(1,4,256), 256, 73728>>>(
        p_Pp, PKROW, (long)NH*NN*PKROW, (long)NN*PKROW,
        p_vT, PKROW, (long)NN*PKROW, (long)DH*PKROW,
        nullptr, 0, 0, 0,  p_at, PKROW, (long)NN*PKROW, 2*DH,
        nullptr, nullptr, 1.f, NN, NH);

    // out = Q + attn @ Wo^T + bo   (fp32 + packed)
    gemm_pk<128, F_F32|F_PK|F_BCOL|F_RESID><<<dim3(4,128,1), 256, 98304>>>(
        p_at, PKROW, 0, 0,  p_wo, PKROW, 0, 0,
        p_of, DD, 0, 0,  p_op, PKROW, 0, 0,  bo, Q, 1.f, 512, 1);

    // h1 = relu(out @ W1^T + b1)
    gemm_pk<128, F_PK|F_BCOL|F_RELU><<<dim3(4,128,1), 256, 98304>>>(
        p_op, PKROW, 0, 0,  p_w1, PKROW, 0, 0,
        nullptr, 0, 0, 0,  p_h1, PKROW, 0, 0,  b1, nullptr, 1.f, 512, 1);

    // final = out + h1 @ W2^T + b2 -> d_out
    gemm_pk<128, F_F32|F_BCOL|F_RESID><<<dim3(4,128,1), 256, 98304>>>(
        p_h1, PKROW, 0, 0,  p_w2, PKROW, 0, 0,
        out, DD, 0, 0,  nullptr, 0, 0, 0,  b2, p_of, 1.f, 512, 1);
}

// round 5
// speedup vs baseline: 1.0045x; 1.0045x over previous
#include <cuda_runtime.h>
#include <cuda_bf16.h>

typedef unsigned short u16;
typedef unsigned int   u32;

#define BB 32
#define NN 512
#define DD 512
#define NH 8
#define DH 64
#define BH (BB*NH)       // 256
#define MROWS (BB*NN)    // 16384
#define PKROW 1024       // packed row: 512 cols -> 16 blocks of [hi32|lo32] u16

// epilogue flags
#define F_F32   1
#define F_PK    2
#define F_BCOL  4
#define F_BROW  8
#define F_RELU  16
#define F_RESID 32

// ---------------- scratch (__device__ globals; no allocations) ----------------
__device__ u16  g_inq [MROWS*PKROW];
__device__ u16  g_ink [MROWS*PKROW];
__device__ u16  g_wq  [DD*PKROW];
__device__ u16  g_wk  [DD*PKROW];
__device__ u16  g_wv  [DD*PKROW];
__device__ u16  g_wo  [DD*PKROW];
__device__ u16  g_w1  [DD*PKROW];
__device__ u16  g_w2  [DD*PKROW];
__device__ u16  g_qp  [MROWS*PKROW];
__device__ u16  g_kp  [MROWS*PKROW];
__device__ u16  g_vT  [MROWS*PKROW];      // [b][d=512][tokens packed]
__device__ u16  g_Pp  [134217728];        // [z=256][q=512][PKROW]
__device__ u16  g_at  [MROWS*PKROW];
__device__ u16  g_op  [MROWS*PKROW];
__device__ u16  g_h1  [MROWS*PKROW];
__device__ float  g_sc  [67108864];       // [z][q][k] fp32 scores
__device__ float  g_of  [MROWS*DD];       // out fp32 (residual source)
__device__ float2 g_st  [BH*NN];          // per (z,k): (max, 1/sum)

// ---------------- helpers ----------------
__device__ __forceinline__ void split2(float x, float y, u32 &h, u32 &l) {
    __nv_bfloat16 hx = __float2bfloat16(x);
    __nv_bfloat16 hy = __float2bfloat16(y);
    __nv_bfloat16 lx = __float2bfloat16(x - __bfloat162float(hx));
    __nv_bfloat16 ly = __float2bfloat16(y - __bfloat162float(hy));
    __nv_bfloat162 H; H.x = hx; H.y = hy;
    __nv_bfloat162 L; L.x = lx; L.y = ly;
    h = *(u32*)&H; l = *(u32*)&L;
}

__device__ __forceinline__ void mma_bf16(float* c, const u32* a, const u32* b) {
    asm volatile(
        "mma.sync.aligned.m16n8k16.row.col.f32.bf16.bf16.f32 "
        "{%0,%1,%2,%3}, {%4,%5,%6,%7}, {%8,%9}, {%0,%1,%2,%3};\n"
        : "+f"(c[0]), "+f"(c[1]), "+f"(c[2]), "+f"(c[3])
        : "r"(a[0]), "r"(a[1]), "r"(a[2]), "r"(a[3]), "r"(b[0]), "r"(b[1]));
}

__device__ __forceinline__ void ldsm4(u32 &r0, u32 &r1, u32 &r2, u32 &r3, const u16* p) {
    u32 a = (u32)__cvta_generic_to_shared(p);
    asm volatile("ldmatrix.sync.aligned.m8n8.x4.shared.b16 {%0,%1,%2,%3}, [%4];\n"
                 : "=r"(r0), "=r"(r1), "=r"(r2), "=r"(r3) : "r"(a));
}

__device__ __forceinline__ void cp16(u16* dst, const u16* src) {
    u32 d = (u32)__cvta_generic_to_shared(dst);
    asm volatile("cp.async.cg.shared.global [%0], [%1], 16;\n" :: "r"(d), "l"(src));
}

// ---------------- prep: fp32 -> packed hi/lo bf16 (rows of 512) ----------------
__global__ void __launch_bounds__(256) split_pack(const float* __restrict__ src,
                                                  u16* __restrict__ dst, int total4) {
    int i = blockIdx.x * 256 + threadIdx.x;
    if (i >= total4) return;
    int m = i >> 7;            // 128 float4 per row
    int k = (i & 127) << 2;
    float4 f = ((const float4*)src)[i];
    long off = (long)m * PKROW + ((k >> 5) << 6) + (k & 31);
    u32 h0, l0, h1, l1;
    split2(f.x, f.y, h0, l0);
    split2(f.z, f.w, h1, l1);
    *(u32*)(dst + off)      = h0;
    *(u32*)(dst + off + 2)  = h1;
    *(u32*)(dst + off + 32) = l0;
    *(u32*)(dst + off + 34) = l1;
}

// ---------------- generic packed NT GEMM, cp.async 3-stage + ldmatrix ----------
template<int BN, int FL>
__global__ void __launch_bounds__(256, 1) gemm_pk(
    const u16* __restrict__ Ap, long aRow, long aZb, long aZh,
    const u16* __restrict__ Bp, long bRow, long bZb, long bZh,
    float* __restrict__ Cf, int ldcf, long cfZb, long cfZh,
    u16* __restrict__ Cp, long cpRow, long cpZb, long cpZh,
    const float* __restrict__ bias,
    const float* __restrict__ Rres,
    float alpha, int K, int Hh)
{
    constexpr int ST  = 3;
    constexpr int MF  = (BN == 128) ? 4 : 2;
    constexpr int ASZ = 128 * 64;       // u16 per A stage
    constexpr int BSZ = BN * 64;

    extern __shared__ u16 sm[];
    u16* sA = sm;
    u16* sB = sm + ST * ASZ;

    const int z  = blockIdx.z;
    const int zb = z / Hh;
    const int zh = z - zb * Hh;
    const u16* Ag = Ap + (long)zb * aZb + (long)zh * aZh + (long)blockIdx.y * 128 * aRow;
    const u16* Bg = Bp + (long)zb * bZb + (long)zh * bZh + (long)blockIdx.x * BN * bRow;

    const int tid = threadIdx.x;
    const int wid = tid >> 5, lane = tid & 31;
    const int wm  = (BN == 128) ? (wid & 1)  : (wid & 3);
    const int wn  = (BN == 128) ? (wid >> 1) : (wid >> 2);
    const int WMb = wm * ((BN == 128) ? 64 : 32);
    const int WNb = wn * 32;
    const int mi  = lane >> 3;
    // ldmatrix lane addressing (constant per thread)
    const int arb = WMb + ((mi & 1) << 3) + (lane & 7);
    const int ar7 = arb & 7;
    const int cA  = mi >> 1;
    const int brb = WNb + ((mi >> 1) << 3) + (lane & 7);
    const int br7 = brb & 7;
    const int cB  = mi & 1;

    float acc[MF][4][4];
    #pragma unroll
    for (int a = 0; a < MF; a++)
        #pragma unroll
        for (int b = 0; b < 4; b++)
            #pragma unroll
            for (int c = 0; c < 4; c++) acc[a][b][c] = 0.f;

    const int KT = K >> 5;

    // prologue: stages 0..ST-2
    #pragma unroll
    for (int s = 0; s < ST - 1; s++) {
        u16* dA = sA + s * ASZ;
        u16* dB = sB + s * BSZ;
        const u16* gA = Ag + s * 64;
        const u16* gB = Bg + s * 64;
        #pragma unroll
        for (int i = 0; i < 4; i++) {
            int id = i * 256 + tid; int r = id >> 3, c = id & 7;
            cp16(dA + r * 64 + ((c ^ (r & 7)) << 3), gA + (long)r * aRow + c * 8);
        }
        #pragma unroll
        for (int i = 0; i < BN / 32; i++) {
            int id = i * 256 + tid; int r = id >> 3, c = id & 7;
            cp16(dB + r * 64 + ((c ^ (r & 7)) << 3), gB + (long)r * bRow + c * 8);
        }
        asm volatile("cp.async.commit_group;\n");
    }

    #pragma unroll 1
    for (int kt = 0; kt < KT; kt++) {
        asm volatile("cp.async.wait_group %0;\n" :: "n"(ST - 2));
        __syncthreads();
        const u16* As = sA + (kt % ST) * ASZ;
        const u16* Bs = sB + (kt % ST) * BSZ;

        #pragma unroll
        for (int s = 0; s < 2; s++) {
            u32 ah[MF][4], al[MF][4], bh[4][2], bl[4][2];
            #pragma unroll
            for (int mf = 0; mf < MF; mf++) {
                const u16* base = As + (arb + mf * 16) * 64;
                ldsm4(ah[mf][0], ah[mf][1], ah[mf][2], ah[mf][3],
                      base + (((2 * s + cA) ^ ar7) << 3));
                ldsm4(al[mf][0], al[mf][1], al[mf][2], al[mf][3],
                      base + (((4 + 2 * s + cA) ^ ar7) << 3));
            }
            #pragma unroll
            for (int g = 0; g < 2; g++) {
                const u16* base = Bs + (brb + g * 16) * 64;
                u32 r0, r1, r2, r3;
                ldsm4(r0, r1, r2, r3, base + (((2 * s + cB) ^ br7) << 3));
                bh[g*2][0] = r0; bh[g*2][1] = r1; bh[g*2+1][0] = r2; bh[g*2+1][1] = r3;
                ldsm4(r0, r1, r2, r3, base + (((4 + 2 * s + cB) ^ br7) << 3));
                bl[g*2][0] = r0; bl[g*2][1] = r1; bl[g*2+1][0] = r2; bl[g*2+1][1] = r3;
            }
            #pragma unroll
            for (int mf = 0; mf < MF; mf++)
                #pragma unroll
                for (int nf = 0; nf < 4; nf++) {
                    mma_bf16(acc[mf][nf], ah[mf], bh[nf]);
                    mma_bf16(acc[mf][nf], ah[mf], bl[nf]);
                    mma_bf16(acc[mf][nf], al[mf], bh[nf]);
                }
        }

        int nk = kt + ST - 1;
        if (nk < KT) {
            u16* dA = sA + (nk % ST) * ASZ;
            u16* dB = sB + (nk % ST) * BSZ;
            const u16* gA = Ag + nk * 64;
            const u16* gB = Bg + nk * 64;
            #pragma unroll
            for (int i = 0; i < 4; i++) {
                int id = i * 256 + tid; int r = id >> 3, c = id & 7;
                cp16(dA + r * 64 + ((c ^ (r & 7)) << 3), gA + (long)r * aRow + c * 8);
            }
            #pragma unroll
            for (int i = 0; i < BN / 32; i++) {
                int id = i * 256 + tid; int r = id >> 3, c = id & 7;
                cp16(dB + r * 64 + ((c ^ (r & 7)) << 3), gB + (long)r * bRow + c * 8);
            }
        }
        asm volatile("cp.async.commit_group;\n");
    }

    // ---------------- epilogue ----------------
    const int lg = lane >> 2, lc = lane & 3;
    const int m0  = blockIdx.y * 128;
    const int n0g = blockIdx.x * BN;
    float* Cfz = (FL & F_F32) ? (Cf + (long)zb * cfZb + (long)zh * cfZh) : nullptr;
    u16*   Cpz = (FL & F_PK)  ? (Cp + (long)zb * cpZb + (long)zh * cpZh) : nullptr;

    #pragma unroll
    for (int mf = 0; mf < MF; mf++) {
        int r1 = m0 + WMb + mf * 16 + lg;
        int r2 = r1 + 8;
        float br1 = 0.f, br2 = 0.f;
        if (FL & F_BROW) { br1 = bias[r1]; br2 = bias[r2]; }
        #pragma unroll
        for (int nf = 0; nf < 4; nf++) {
            int n = n0g + WNb + nf * 8 + lc * 2;
            float c0 = acc[mf][nf][0] * alpha, c1 = acc[mf][nf][1] * alpha;
            float c2 = acc[mf][nf][2] * alpha, c3 = acc[mf][nf][3] * alpha;
            if (FL & F_BCOL) {
                float2 bb = *(const float2*)(bias + n);
                c0 += bb.x; c1 += bb.y; c2 += bb.x; c3 += bb.y;
            }
            if (FL & F_BROW) { c0 += br1; c1 += br1; c2 += br2; c3 += br2; }
            if (FL & F_RESID) {
                float2 q1 = *(const float2*)(Rres + (long)r1 * ldcf + n);
                float2 q2 = *(const float2*)(Rres + (long)r2 * ldcf + n);
                c0 += q1.x; c1 += q1.y; c2 += q2.x; c3 += q2.y;
            }
            if (FL & F_RELU) {
                c0 = fmaxf(c0, 0.f); c1 = fmaxf(c1, 0.f);
                c2 = fmaxf(c2, 0.f); c3 = fmaxf(c3, 0.f);
            }
            if (FL & F_F32) {
                *(float2*)(Cfz + (long)r1 * ldcf + n) = make_float2(c0, c1);
                *(float2*)(Cfz + (long)r2 * ldcf + n) = make_float2(c2, c3);
            }
            if (FL & F_PK) {
                u32 h, l;
                long o1 = (long)r1 * cpRow + ((n >> 5) << 6) + (n & 31);
                split2(c0, c1, h, l);
                *(u32*)(Cpz + o1) = h; *(u32*)(Cpz + o1 + 32) = l;
                long o2 = (long)r2 * cpRow + ((n >> 5) << 6) + (n & 31);
                split2(c2, c3, h, l);
                *(u32*)(Cpz + o2) = h; *(u32*)(Cpz + o2 + 32) = l;
            }
        }
    }
}

// ---------------- softmax over QUERY axis ----------------
__global__ void __launch_bounds__(256) softmax_pass1(const float* __restrict__ S,
                                                     float2* __restrict__ stat) {
    const int z = blockIdx.y;
    const int k = blockIdx.x * 256 + threadIdx.x;
    const float* p = S + (long)z * NN * NN + k;
    float mx = -1e30f, s = 0.f;
    #pragma unroll 4
    for (int q = 0; q < NN; q++) {
        float x = p[(long)q * NN];
        float nm = fmaxf(mx, x);
        s = s * __expf(mx - nm) + __expf(x - nm);
        mx = nm;
    }
    stat[z * NN + k] = make_float2(mx, 1.0f / s);
}

__global__ void __launch_bounds__(256) softmax_pass2(const float* __restrict__ S,
                                                     const float2* __restrict__ stat,
                                                     u16* __restrict__ P) {
    const int z = blockIdx.y;
    const int q = blockIdx.x;
    const int k = threadIdx.x * 2;
    float2 x  = *(const float2*)(S + ((long)z * NN + q) * NN + k);
    float2 s0 = stat[z * NN + k];
    float2 s1 = stat[z * NN + k + 1];
    float p0 = __expf(x.x - s0.x) * s0.y;
    float p1 = __expf(x.y - s1.x) * s1.y;
    u32 h, l;
    split2(p0, p1, h, l);
    long off = ((long)z * NN + q) * PKROW + ((k >> 5) << 6) + (k & 31);
    *(u32*)(P + off)      = h;
    *(u32*)(P + off + 32) = l;
}

// ---------------- launch ----------------
extern "C" void kernel_launch(void* const* d_in, const int* in_sizes, int n_in,
                              void* d_out, int out_size)
{
    const float* Q  = (const float*)d_in[0];
    const float* Kx = (const float*)d_in[1];
    const float* Wq = (const float*)d_in[2];
    const float* bq = (const float*)d_in[3];
    const float* Wk = (const float*)d_in[4];
    const float* bk = (const float*)d_in[5];
    const float* Wv = (const float*)d_in[6];
    const float* bv = (const float*)d_in[7];
    const float* Wo = (const float*)d_in[8];
    const float* bo = (const float*)d_in[9];
    const float* W1 = (const float*)d_in[10];
    const float* b1 = (const float*)d_in[11];
    const float* W2 = (const float*)d_in[12];
    const float* b2 = (const float*)d_in[13];
    float* out = (float*)d_out;

    static u16 *p_inq = nullptr, *p_ink, *p_wq, *p_wk, *p_wv, *p_wo, *p_w1, *p_w2;
    static u16 *p_qp, *p_kp, *p_vT, *p_Pp, *p_at, *p_op, *p_h1;
    static float *p_sc, *p_of;
    static float2 *p_st;
    if (!p_inq) {
        cudaGetSymbolAddress((void**)&p_ink, g_ink);
        cudaGetSymbolAddress((void**)&p_wq,  g_wq);
        cudaGetSymbolAddress((void**)&p_wk,  g_wk);
        cudaGetSymbolAddress((void**)&p_wv,  g_wv);
        cudaGetSymbolAddress((void**)&p_wo,  g_wo);
        cudaGetSymbolAddress((void**)&p_w1,  g_w1);
        cudaGetSymbolAddress((void**)&p_w2,  g_w2);
        cudaGetSymbolAddress((void**)&p_qp,  g_qp);
        cudaGetSymbolAddress((void**)&p_kp,  g_kp);
        cudaGetSymbolAddress((void**)&p_vT,  g_vT);
        cudaGetSymbolAddress((void**)&p_Pp,  g_Pp);
        cudaGetSymbolAddress((void**)&p_at,  g_at);
        cudaGetSymbolAddress((void**)&p_op,  g_op);
        cudaGetSymbolAddress((void**)&p_h1,  g_h1);
        cudaGetSymbolAddress((void**)&p_sc,  g_sc);
        cudaGetSymbolAddress((void**)&p_of,  g_of);
        cudaGetSymbolAddress((void**)&p_st,  g_st);

        cudaFuncSetAttribute((const void*)gemm_pk<128, F_PK|F_BCOL>,
                             cudaFuncAttributeMaxDynamicSharedMemorySize, 98304);
        cudaFuncSetAttribute((const void*)gemm_pk<128, F_PK|F_BROW>,
                             cudaFuncAttributeMaxDynamicSharedMemorySize, 98304);
        cudaFuncSetAttribute((const void*)gemm_pk<128, F_F32>,
                             cudaFuncAttributeMaxDynamicSharedMemorySize, 98304);
        cudaFuncSetAttribute((const void*)gemm_pk<64, F_PK>,
                             cudaFuncAttributeMaxDynamicSharedMemorySize, 73728);
        cudaFuncSetAttribute((const void*)gemm_pk<128, F_F32|F_PK|F_BCOL|F_RESID>,
                             cudaFuncAttributeMaxDynamicSharedMemorySize, 98304);
        cudaFuncSetAttribute((const void*)gemm_pk<128, F_PK|F_BCOL|F_RELU>,
                             cudaFuncAttributeMaxDynamicSharedMemorySize, 98304);
        cudaFuncSetAttribute((const void*)gemm_pk<128, F_F32|F_BCOL|F_RESID>,
                             cudaFuncAttributeMaxDynamicSharedMemorySize, 98304);

        cudaGetSymbolAddress((void**)&p_inq, g_inq); // last: guards the others
    }

    const float SCALE = 0.044194173824159216f;  // 1/sqrt(512)

    // prep: split to packed bf16 hi/lo
    split_pack<<<8192, 256>>>(Q,  p_inq, MROWS * 128);
    split_pack<<<8192, 256>>>(Kx, p_ink, MROWS * 128);
    split_pack<<<256, 256>>>(Wq, p_wq, DD * 128);
    split_pack<<<256, 256>>>(Wk, p_wk, DD * 128);
    split_pack<<<256, 256>>>(Wv, p_wv, DD * 128);
    split_pack<<<256, 256>>>(Wo, p_wo, DD * 128);
    split_pack<<<256, 256>>>(W1, p_w1, DD * 128);
    split_pack<<<256, 256>>>(W2, p_w2, DD * 128);

    // q, k projections
    gemm_pk<128, F_PK|F_BCOL><<<dim3(4,128,1), 256, 98304>>>(
        p_inq, PKROW, 0, 0,  p_wq, PKROW, 0, 0,
        nullptr, 0, 0, 0,  p_qp, PKROW, 0, 0,  bq, nullptr, 1.f, 512, 1);
    gemm_pk<128, F_PK|F_BCOL><<<dim3(4,128,1), 256, 98304>>>(
        p_ink, PKROW, 0, 0,  p_wk, PKROW, 0, 0,
        nullptr, 0, 0, 0,  p_kp, PKROW, 0, 0,  bk, nullptr, 1.f, 512, 1);

    // vT[b] = Wv @ Kx[b]^T  (row bias bv)
    gemm_pk<128, F_PK|F_BROW><<<dim3(4,4,32), 256, 98304>>>(
        p_wv, PKROW, 0, 0,  p_ink, PKROW, (long)NN*PKROW, 0,
        nullptr, 0, 0, 0,  p_vT, PKROW, (long)NN*PKROW, 0,  bv, nullptr, 1.f, 512, 1);

    // scores (fp32, scaled)
    gemm_pk<128, F_F32><<<dim3(4,4,256), 256, 98304>>>(
        p_qp, PKROW, (long)NN*PKROW, 2*DH,  p_kp, PKROW, (long)NN*PKROW, 2*DH,
        p_sc, NN, (long)NH*NN*NN, (long)NN*NN,  nullptr, 0, 0, 0,
        nullptr, nullptr, SCALE, DH, NH);

    // softmax over q (per column k), write packed P
    softmax_pass1<<<dim3(2, BH), 256>>>(p_sc, p_st);
    softmax_pass2<<<dim3(NN, BH), 256>>>(p_sc, p_st, p_Pp);

    // attn = P @ vT^T  (per (b,h), BN=64)
    gemm_pk<64, F_PK><<<dim3(1,4,256), 256, 73728>>>(
        p_Pp, PKROW, (long)NH*NN*PKROW, (long)NN*PKROW,
        p_vT, PKROW, (long)NN*PKROW, (long)DH*PKROW,
        nullptr, 0, 0, 0,  p_at, PKROW, (long)NN*PKROW, 2*DH,
        nullptr, nullptr, 1.f, NN, NH);

    // out = Q + attn @ Wo^T + bo   (fp32 + packed)
    gemm_pk<128, F_F32|F_PK|F_BCOL|F_RESID><<<dim3(4,128,1), 256, 98304>>>(
        p_at, PKROW, 0, 0,  p_wo, PKROW, 0, 0,
        p_of, DD, 0, 0,  p_op, PKROW, 0, 0,  bo, Q, 1.f, 512, 1);

    // h1 = relu(out @ W1^T + b1)
    gemm_pk<128, F_PK|F_BCOL|F_RELU><<<dim3(4,128,1), 256, 98304>>>(
        p_op, PKROW, 0, 0,  p_w1, PKROW, 0, 0,
        nullptr, 0, 0, 0,  p_h1, PKROW, 0, 0,  b1, nullptr, 1.f, 512, 1);

    // final = out + h1 @ W2^T + b2 -> d_out
    gemm_pk<128, F_F32|F_BCOL|F_RESID><<<dim3(4,128,1), 256, 98304>>>(
        p_h1, PKROW, 0, 0,  p_w2, PKROW, 0, 0,
        out, DD, 0, 0,  nullptr, 0, 0, 0,  b2, p_of, 1.f, 512, 1);
}